// round 15
// baseline (speedup 1.0000x reference)
#include <cuda_runtime.h>
#include <cuda_fp16.h>
#include <cuda_bf16.h>
#include <cstdint>

#define N_NODES 100000
#define D 32
#define TILE_NODES 64
#define TILE_VEC   (TILE_NODES * 8)   // 512 float4 per tile

// Aggregation scratch, padded by one tile so the cp.async pipeline can read
// a full final tile without OOB (padding rows computed, never stored).
__device__ float g_agg[(N_NODES + TILE_NODES) * D];
// fp16 copy of x: 100000 x 32 halves = 6.4 MB (row = 64B = 4 x uint4)
__device__ uint4 g_xh[N_NODES * 4];

// ---------------------------------------------------------------------------
// Convert x (fp32) -> g_xh (fp16). Each thread handles 8 floats -> 16B.
// ---------------------------------------------------------------------------
__global__ void convert_kernel(const float4* __restrict__ x4,
                               uint4* __restrict__ xh, int n_vec8) {
    int i = blockIdx.x * blockDim.x + threadIdx.x;
    if (i < n_vec8) {
        float4 a = __ldg(x4 + 2 * i);
        float4 b = __ldg(x4 + 2 * i + 1);
        __half2 h0 = __floats2half2_rn(a.x, a.y);
        __half2 h1 = __floats2half2_rn(a.z, a.w);
        __half2 h2 = __floats2half2_rn(b.x, b.y);
        __half2 h3 = __floats2half2_rn(b.z, b.w);
        uint4 o;
        o.x = *reinterpret_cast<unsigned*>(&h0);
        o.y = *reinterpret_cast<unsigned*>(&h1);
        o.z = *reinterpret_cast<unsigned*>(&h2);
        o.w = *reinterpret_cast<unsigned*>(&h3);
        xh[i] = o;
    }
}

// ---------------------------------------------------------------------------
// Scatter: 4 lanes per edge, 8 edges per warp. Each lane gathers one uint4
// (16B = 8 halves) of the 64B fp16 source row, converts to fp32 in-register,
// and issues two red.global.add.v4.f32 (fp32 accumulation, no precision
// loss beyond input quantization). LTS bytes/edge: 64 gather + 128 RED
// (was 128 + 128) -> scatter traffic 410MB -> 307MB.
// ---------------------------------------------------------------------------
__global__ void scatter_kernel(const uint4* __restrict__ xh,
                               const int* __restrict__ edge_index,
                               float* __restrict__ agg,
                               int n_edges) {
    int lane = threadIdx.x & 31;
    int sub  = lane >> 2;   // which of the 8 edges this warp handles
    int q    = lane & 3;    // which 16B quarter of the 64B fp16 row

    int warp0   = (blockIdx.x * blockDim.x + threadIdx.x) >> 5;
    int wstride = (gridDim.x * blockDim.x) >> 5;

    for (int e0 = warp0 * 8; e0 < n_edges; e0 += wstride * 8) {
        int e = e0 + sub;
        if (e < n_edges) {
            int src = __ldg(edge_index + e);            // row 0: src
            int dst = __ldg(edge_index + n_edges + e);  // row 1: dst

            uint4 raw = __ldg(&xh[(size_t)src * 4 + q]);
            __half2 h0 = *reinterpret_cast<__half2*>(&raw.x);
            __half2 h1 = *reinterpret_cast<__half2*>(&raw.y);
            __half2 h2 = *reinterpret_cast<__half2*>(&raw.z);
            __half2 h3 = *reinterpret_cast<__half2*>(&raw.w);
            float2 f0 = __half22float2(h0);
            float2 f1 = __half22float2(h1);
            float2 f2 = __half22float2(h2);
            float2 f3 = __half22float2(h3);

            float* p = agg + (size_t)dst * D + q * 8;
            asm volatile(
                "red.global.add.v4.f32 [%0], {%1, %2, %3, %4};"
                :: "l"(p), "f"(f0.x), "f"(f0.y), "f"(f1.x), "f"(f1.y)
                : "memory");
            asm volatile(
                "red.global.add.v4.f32 [%0], {%1, %2, %3, %4};"
                :: "l"(p + 4), "f"(f2.x), "f"(f2.y), "f"(f3.x), "f"(f3.y)
                : "memory");
        }
    }
}

// ---------------------------------------------------------------------------
// GEMM: out = agg @ W^T, W is [32, 32]. (Measured-best R10 config.)
// Persistent blocks (296 = 2/SM), 256 threads = 8 warps; tile = 64 nodes.
// 3-stage cp.async pipeline; W row per lane as f32x2 pairs; FFMA2 inner loop.
// ---------------------------------------------------------------------------
__device__ __forceinline__ void cp_async16(void* smem, const void* gmem) {
    uint32_t s = (uint32_t)__cvta_generic_to_shared(smem);
    asm volatile("cp.async.ca.shared.global [%0], [%1], 16;"
                 :: "r"(s), "l"(gmem) : "memory");
}

#define PACK2(dst, lo, hi) \
    asm("mov.b64 %0, {%1, %2};" : "=l"(dst) : "f"(lo), "f"(hi))
#define UNPACK2(lo, hi, src) \
    asm("mov.b64 {%0, %1}, %2;" : "=f"(lo), "=f"(hi) : "l"(src))
#define FMA2(d, a, b, c) \
    asm("fma.rn.f32x2 %0, %1, %2, %3;" : "=l"(d) : "l"(a), "l"(b), "l"(c))

__global__ __launch_bounds__(256)
void gemm_kernel(const float4* __restrict__ agg4,
                 const float* __restrict__ W,
                 float* __restrict__ out,
                 int n_nodes, int ntiles) {
    __shared__ float4 As[3][TILE_VEC];  // 3 x 8KB
    __shared__ float  Ws[D * 33];       // padded, conflict-free

    int tid  = threadIdx.x;
    int lane = tid & 31;   // output feature j
    int wid  = tid >> 5;   // warp: nodes [wid*8, wid*8+8) of the tile

    // Stage W coalesced (once per block)
#pragma unroll
    for (int i = tid; i < D * D; i += 256)
        Ws[(i >> 5) * 33 + (i & 31)] = W[i];

    // Prologue: issue copies for this block's first two tiles
    int t0 = blockIdx.x;
    if (t0 < ntiles) {
        const float4* g = agg4 + (size_t)t0 * TILE_VEC;
        cp_async16(&As[0][tid], g + tid);
        cp_async16(&As[0][tid + 256], g + tid + 256);
        asm volatile("cp.async.commit_group;" ::: "memory");
    }
    int t1 = t0 + gridDim.x;
    if (t1 < ntiles) {
        const float4* g = agg4 + (size_t)t1 * TILE_VEC;
        cp_async16(&As[1][tid], g + tid);
        cp_async16(&As[1][tid + 256], g + tid + 256);
        asm volatile("cp.async.commit_group;" ::: "memory");
    }

    __syncthreads();   // Ws visible (also first pipeline barrier)

    // Lane j's W row as 16 packed f32x2 pairs
    unsigned long long w2[D / 2];
#pragma unroll
    for (int p = 0; p < D / 2; ++p)
        PACK2(w2[p], Ws[lane * 33 + 2 * p], Ws[lane * 33 + 2 * p + 1]);

    int k = 0;
    for (int tile = t0; tile < ntiles; tile += gridDim.x, ++k) {
        int buf = k % 3;

        asm volatile("cp.async.wait_group 1;" ::: "memory");
        __syncthreads();

        int nt = tile + 2 * gridDim.x;
        if (nt < ntiles) {
            int nbuf = (k + 2) % 3;
            const float4* g = agg4 + (size_t)nt * TILE_VEC;
            cp_async16(&As[nbuf][tid], g + tid);
            cp_async16(&As[nbuf][tid + 256], g + tid + 256);
            asm volatile("cp.async.commit_group;" ::: "memory");
        }

        unsigned long long acc2[8];
#pragma unroll
        for (int r = 0; r < 8; ++r) acc2[r] = 0ull;

        const float4* Ab = &As[buf][wid * 64];
#pragma unroll
        for (int k4 = 0; k4 < 8; ++k4) {
#pragma unroll
            for (int r = 0; r < 8; ++r) {
                float4 a = Ab[r * 8 + k4];   // broadcast LDS.128
                unsigned long long a01, a23;
                PACK2(a01, a.x, a.y);
                PACK2(a23, a.z, a.w);
                FMA2(acc2[r], a01, w2[k4 * 2 + 0], acc2[r]);
                FMA2(acc2[r], a23, w2[k4 * 2 + 1], acc2[r]);
            }
        }

        int node0 = tile * TILE_NODES + wid * 8;
#pragma unroll
        for (int r = 0; r < 8; ++r) {
            int node = node0 + r;
            if (node < n_nodes) {
                float lo, hi;
                UNPACK2(lo, hi, acc2[r]);
                out[(size_t)node * D + lane] = lo + hi;   // coalesced
            }
        }
    }
}

// ---------------------------------------------------------------------------
extern "C" void kernel_launch(void* const* d_in, const int* in_sizes, int n_in,
                              void* d_out, int out_size) {
    const float* x = (const float*)d_in[0];
    const int* edge_index = (const int*)d_in[1];
    const float* W = (const float*)d_in[2];
    float* out = (float*)d_out;

    int n_edges = in_sizes[1] / 2;
    int n_nodes = in_sizes[0] / D;

    float* agg;
    cudaGetSymbolAddress((void**)&agg, g_agg);
    uint4* xh;
    cudaGetSymbolAddress((void**)&xh, g_xh);

    // 1) zero the aggregation buffer
    cudaMemsetAsync(agg, 0, (size_t)N_NODES * D * sizeof(float));

    // 2) convert x -> fp16 (halves the scatter gather bytes)
    {
        int n_vec8 = n_nodes * D / 8;   // 400000
        convert_kernel<<<(n_vec8 + 255) / 256, 256>>>((const float4*)x, xh,
                                                      n_vec8);
    }

    // 3) scatter-add: 8 edges per warp, fp16 gather + fp32 vector RED
    {
        int threads = 256;   // 8 warps
        int blocks  = 4736;
        scatter_kernel<<<blocks, threads>>>(xh, edge_index, agg, n_edges);
    }

    // 4) GEMM: persistent cp.async-pipelined blocks (2/SM), 64-node tiles
    {
        int ntiles = (n_nodes + TILE_NODES - 1) / TILE_NODES;  // 1563
        gemm_kernel<<<296, 256>>>((const float4*)agg, W, out, n_nodes, ntiles);
    }
}

// round 16
// speedup vs baseline: 1.2236x; 1.2236x over previous
#include <cuda_runtime.h>
#include <cuda_bf16.h>
#include <cstdint>

#define N_NODES 100000
#define D 32
#define TILE_NODES 64
#define TILE_VEC   (TILE_NODES * 8)   // 512 float4 per tile

// Transformed features y = x @ W^T, padded by one tile for the cp.async
// pipeline (padding rows computed, never stored).
__device__ float g_y[(N_NODES + TILE_NODES) * D];

// ---------------------------------------------------------------------------
// Transform: y = x @ W^T, W is [32, 32]. (Tuned R10 GEMM config.)
// Persistent blocks (296 = 2/SM), 256 threads = 8 warps; tile = 64 nodes.
// 3-stage cp.async pipeline; W row per lane as f32x2 pairs; FFMA2 inner loop.
// ---------------------------------------------------------------------------
__device__ __forceinline__ void cp_async16(void* smem, const void* gmem) {
    uint32_t s = (uint32_t)__cvta_generic_to_shared(smem);
    asm volatile("cp.async.ca.shared.global [%0], [%1], 16;"
                 :: "r"(s), "l"(gmem) : "memory");
}

#define PACK2(dst, lo, hi) \
    asm("mov.b64 %0, {%1, %2};" : "=l"(dst) : "f"(lo), "f"(hi))
#define UNPACK2(lo, hi, src) \
    asm("mov.b64 {%0, %1}, %2;" : "=f"(lo), "=f"(hi) : "l"(src))
#define FMA2(d, a, b, c) \
    asm("fma.rn.f32x2 %0, %1, %2, %3;" : "=l"(d) : "l"(a), "l"(b), "l"(c))

__global__ __launch_bounds__(256)
void transform_kernel(const float4* __restrict__ x4,
                      const float* __restrict__ W,
                      float* __restrict__ y,
                      int n_nodes, int ntiles) {
    __shared__ float4 As[3][TILE_VEC];  // 3 x 8KB
    __shared__ float  Ws[D * 33];       // padded, conflict-free

    int tid  = threadIdx.x;
    int lane = tid & 31;   // output feature j
    int wid  = tid >> 5;   // warp: nodes [wid*8, wid*8+8) of the tile

    // Stage W coalesced (once per block)
#pragma unroll
    for (int i = tid; i < D * D; i += 256)
        Ws[(i >> 5) * 33 + (i & 31)] = W[i];

    // Prologue: issue copies for this block's first two tiles
    int t0 = blockIdx.x;
    if (t0 < ntiles) {
        const float4* g = x4 + (size_t)t0 * TILE_VEC;
        cp_async16(&As[0][tid], g + tid);
        cp_async16(&As[0][tid + 256], g + tid + 256);
        asm volatile("cp.async.commit_group;" ::: "memory");
    }
    int t1 = t0 + gridDim.x;
    if (t1 < ntiles) {
        const float4* g = x4 + (size_t)t1 * TILE_VEC;
        cp_async16(&As[1][tid], g + tid);
        cp_async16(&As[1][tid + 256], g + tid + 256);
        asm volatile("cp.async.commit_group;" ::: "memory");
    }

    __syncthreads();   // Ws visible (also first pipeline barrier)

    // Lane j's W row as 16 packed f32x2 pairs
    unsigned long long w2[D / 2];
#pragma unroll
    for (int p = 0; p < D / 2; ++p)
        PACK2(w2[p], Ws[lane * 33 + 2 * p], Ws[lane * 33 + 2 * p + 1]);

    int k = 0;
    for (int tile = t0; tile < ntiles; tile += gridDim.x, ++k) {
        int buf = k % 3;

        asm volatile("cp.async.wait_group 1;" ::: "memory");
        __syncthreads();

        int nt = tile + 2 * gridDim.x;
        if (nt < ntiles) {
            int nbuf = (k + 2) % 3;
            const float4* g = x4 + (size_t)nt * TILE_VEC;
            cp_async16(&As[nbuf][tid], g + tid);
            cp_async16(&As[nbuf][tid + 256], g + tid + 256);
            asm volatile("cp.async.commit_group;" ::: "memory");
        }

        unsigned long long acc2[8];
#pragma unroll
        for (int r = 0; r < 8; ++r) acc2[r] = 0ull;

        const float4* Ab = &As[buf][wid * 64];
#pragma unroll
        for (int k4 = 0; k4 < 8; ++k4) {
#pragma unroll
            for (int r = 0; r < 8; ++r) {
                float4 a = Ab[r * 8 + k4];   // broadcast LDS.128
                unsigned long long a01, a23;
                PACK2(a01, a.x, a.y);
                PACK2(a23, a.z, a.w);
                FMA2(acc2[r], a01, w2[k4 * 2 + 0], acc2[r]);
                FMA2(acc2[r], a23, w2[k4 * 2 + 1], acc2[r]);
            }
        }

        int node0 = tile * TILE_NODES + wid * 8;
#pragma unroll
        for (int r = 0; r < 8; ++r) {
            int node = node0 + r;
            if (node < n_nodes) {
                float lo, hi;
                UNPACK2(lo, hi, acc2[r]);
                y[(size_t)node * D + lane] = lo + hi;   // coalesced
            }
        }
    }
}

// ---------------------------------------------------------------------------
// Scatter: 8 lanes per edge, 4 edges per warp (proven R10 shape). Each lane
// gathers one float4 of the 128B transformed row y[src] and issues a
// vectorized red.global.add.v4.f32 directly into out[dst].
// ---------------------------------------------------------------------------
__global__ void scatter_kernel(const float4* __restrict__ y4,
                               const int* __restrict__ edge_index,
                               float* __restrict__ out,
                               int n_edges) {
    int lane = threadIdx.x & 31;
    int sub  = lane >> 3;   // which of the 4 edges this warp handles
    int q    = lane & 7;    // which 16B quarter of the 128B row

    int warp0   = (blockIdx.x * blockDim.x + threadIdx.x) >> 5;
    int wstride = (gridDim.x * blockDim.x) >> 5;

    for (int e0 = warp0 * 4; e0 < n_edges; e0 += wstride * 4) {
        int e = e0 + sub;
        if (e < n_edges) {
            int src = __ldg(edge_index + e);            // row 0: src
            int dst = __ldg(edge_index + n_edges + e);  // row 1: dst

            float4 v = __ldg(&y4[(size_t)src * 8 + q]);
            float* p = out + (size_t)dst * D + q * 4;
            asm volatile(
                "red.global.add.v4.f32 [%0], {%1, %2, %3, %4};"
                :: "l"(p), "f"(v.x), "f"(v.y), "f"(v.z), "f"(v.w)
                : "memory");
        }
    }
}

// ---------------------------------------------------------------------------
extern "C" void kernel_launch(void* const* d_in, const int* in_sizes, int n_in,
                              void* d_out, int out_size) {
    const float* x = (const float*)d_in[0];
    const int* edge_index = (const int*)d_in[1];
    const float* W = (const float*)d_in[2];
    float* out = (float*)d_out;

    int n_edges = in_sizes[1] / 2;
    int n_nodes = in_sizes[0] / D;

    float* y;
    cudaGetSymbolAddress((void**)&y, g_y);

    // 1) zero the output (it is the scatter accumulator now; poisoned 0xAA)
    cudaMemsetAsync(out, 0, (size_t)out_size * sizeof(float));

    // 2) transform: y = x @ W^T  (linear layer commuted through segment_sum)
    {
        int ntiles = (n_nodes + TILE_NODES - 1) / TILE_NODES;  // 1563
        transform_kernel<<<296, 256>>>((const float4*)x, W, y, n_nodes,
                                       ntiles);
    }

    // 3) scatter-add y[src] -> out[dst]: 4 edges/warp, vector RED
    {
        int threads = 256;   // 8 warps
        int blocks  = 4736;
        scatter_kernel<<<blocks, threads>>>((const float4*)y, edge_index, out,
                                            n_edges);
    }
}

// round 17
// speedup vs baseline: 1.3827x; 1.1300x over previous
#include <cuda_runtime.h>
#include <cuda_bf16.h>
#include <cstdint>

#define N_NODES 100000
#define D 32
#define TILE_NODES 64
#define TILE_VEC   (TILE_NODES * 8)   // 512 float4 per tile

// Transformed features y = x @ W^T, padded by one tile for the cp.async
// pipeline (padding rows computed, never stored).
__device__ float g_y[(N_NODES + TILE_NODES) * D];

// ---------------------------------------------------------------------------
// Transform: y = x @ W^T, W is [32, 32]. (Tuned R10 GEMM config.)
// ---------------------------------------------------------------------------
__device__ __forceinline__ void cp_async16(void* smem, const void* gmem) {
    uint32_t s = (uint32_t)__cvta_generic_to_shared(smem);
    asm volatile("cp.async.ca.shared.global [%0], [%1], 16;"
                 :: "r"(s), "l"(gmem) : "memory");
}

#define PACK2(dst, lo, hi) \
    asm("mov.b64 %0, {%1, %2};" : "=l"(dst) : "f"(lo), "f"(hi))
#define UNPACK2(lo, hi, src) \
    asm("mov.b64 {%0, %1}, %2;" : "=f"(lo), "=f"(hi) : "l"(src))
#define FMA2(d, a, b, c) \
    asm("fma.rn.f32x2 %0, %1, %2, %3;" : "=l"(d) : "l"(a), "l"(b), "l"(c))

__global__ __launch_bounds__(256)
void transform_kernel(const float4* __restrict__ x4,
                      const float* __restrict__ W,
                      float* __restrict__ y,
                      int n_nodes, int ntiles) {
    __shared__ float4 As[3][TILE_VEC];  // 3 x 8KB
    __shared__ float  Ws[D * 33];       // padded, conflict-free

    int tid  = threadIdx.x;
    int lane = tid & 31;   // output feature j
    int wid  = tid >> 5;   // warp: nodes [wid*8, wid*8+8) of the tile

#pragma unroll
    for (int i = tid; i < D * D; i += 256)
        Ws[(i >> 5) * 33 + (i & 31)] = W[i];

    int t0 = blockIdx.x;
    if (t0 < ntiles) {
        const float4* g = x4 + (size_t)t0 * TILE_VEC;
        cp_async16(&As[0][tid], g + tid);
        cp_async16(&As[0][tid + 256], g + tid + 256);
        asm volatile("cp.async.commit_group;" ::: "memory");
    }
    int t1 = t0 + gridDim.x;
    if (t1 < ntiles) {
        const float4* g = x4 + (size_t)t1 * TILE_VEC;
        cp_async16(&As[1][tid], g + tid);
        cp_async16(&As[1][tid + 256], g + tid + 256);
        asm volatile("cp.async.commit_group;" ::: "memory");
    }

    __syncthreads();

    unsigned long long w2[D / 2];
#pragma unroll
    for (int p = 0; p < D / 2; ++p)
        PACK2(w2[p], Ws[lane * 33 + 2 * p], Ws[lane * 33 + 2 * p + 1]);

    int k = 0;
    for (int tile = t0; tile < ntiles; tile += gridDim.x, ++k) {
        int buf = k % 3;

        asm volatile("cp.async.wait_group 1;" ::: "memory");
        __syncthreads();

        int nt = tile + 2 * gridDim.x;
        if (nt < ntiles) {
            int nbuf = (k + 2) % 3;
            const float4* g = x4 + (size_t)nt * TILE_VEC;
            cp_async16(&As[nbuf][tid], g + tid);
            cp_async16(&As[nbuf][tid + 256], g + tid + 256);
            asm volatile("cp.async.commit_group;" ::: "memory");
        }

        unsigned long long acc2[8];
#pragma unroll
        for (int r = 0; r < 8; ++r) acc2[r] = 0ull;

        const float4* Ab = &As[buf][wid * 64];
#pragma unroll
        for (int k4 = 0; k4 < 8; ++k4) {
#pragma unroll
            for (int r = 0; r < 8; ++r) {
                float4 a = Ab[r * 8 + k4];   // broadcast LDS.128
                unsigned long long a01, a23;
                PACK2(a01, a.x, a.y);
                PACK2(a23, a.z, a.w);
                FMA2(acc2[r], a01, w2[k4 * 2 + 0], acc2[r]);
                FMA2(acc2[r], a23, w2[k4 * 2 + 1], acc2[r]);
            }
        }

        int node0 = tile * TILE_NODES + wid * 8;
#pragma unroll
        for (int r = 0; r < 8; ++r) {
            int node = node0 + r;
            if (node < n_nodes) {
                float lo, hi;
                UNPACK2(lo, hi, acc2[r]);
                y[(size_t)node * D + lane] = lo + hi;   // coalesced
            }
        }
    }
}

// ---------------------------------------------------------------------------
// Scatter: 8 lanes per edge, 4 edges per warp, UNROLLED x2 (8 edges per
// iteration as two independent groups) to double memory-level parallelism
// on the idx->gather->RED chain. Gathers use __ldcg (L2-only; L1 hit rate
// for the 205MB random stream is ~0).
// ---------------------------------------------------------------------------
__global__ void scatter_kernel(const float4* __restrict__ y4,
                               const int* __restrict__ edge_index,
                               float* __restrict__ out,
                               int n_edges) {
    int lane = threadIdx.x & 31;
    int sub  = lane >> 3;   // which of the 4 edges per group
    int q    = lane & 7;    // which 16B quarter of the 128B row

    int warp0   = (blockIdx.x * blockDim.x + threadIdx.x) >> 5;
    int wstride = (gridDim.x * blockDim.x) >> 5;

    for (int e0 = warp0 * 8; e0 < n_edges; e0 += wstride * 8) {
        int eA = e0 + sub;
        int eB = e0 + 4 + sub;
        bool vA = eA < n_edges;
        bool vB = eB < n_edges;

        // Issue both index pairs first (independent)
        int srcA = 0, dstA = 0, srcB = 0, dstB = 0;
        if (vA) { srcA = __ldg(edge_index + eA);
                  dstA = __ldg(edge_index + n_edges + eA); }
        if (vB) { srcB = __ldg(edge_index + eB);
                  dstB = __ldg(edge_index + n_edges + eB); }

        // Both gathers in flight together
        float4 a = make_float4(0.f, 0.f, 0.f, 0.f), b = a;
        if (vA) a = __ldcg(&y4[(size_t)srcA * 8 + q]);
        if (vB) b = __ldcg(&y4[(size_t)srcB * 8 + q]);

        if (vA) {
            float* p = out + (size_t)dstA * D + q * 4;
            asm volatile(
                "red.global.add.v4.f32 [%0], {%1, %2, %3, %4};"
                :: "l"(p), "f"(a.x), "f"(a.y), "f"(a.z), "f"(a.w)
                : "memory");
        }
        if (vB) {
            float* p = out + (size_t)dstB * D + q * 4;
            asm volatile(
                "red.global.add.v4.f32 [%0], {%1, %2, %3, %4};"
                :: "l"(p), "f"(b.x), "f"(b.y), "f"(b.z), "f"(b.w)
                : "memory");
        }
    }
}

// ---------------------------------------------------------------------------
extern "C" void kernel_launch(void* const* d_in, const int* in_sizes, int n_in,
                              void* d_out, int out_size) {
    const float* x = (const float*)d_in[0];
    const int* edge_index = (const int*)d_in[1];
    const float* W = (const float*)d_in[2];
    float* out = (float*)d_out;

    int n_edges = in_sizes[1] / 2;
    int n_nodes = in_sizes[0] / D;

    float* y;
    cudaGetSymbolAddress((void**)&y, g_y);

    // 1) zero the output (scatter accumulator; also warms it into L2)
    cudaMemsetAsync(out, 0, (size_t)out_size * sizeof(float));

    // 2) transform: y = x @ W^T (linear layer commuted through segment_sum)
    {
        int ntiles = (n_nodes + TILE_NODES - 1) / TILE_NODES;  // 1563
        transform_kernel<<<296, 256>>>((const float4*)x, W, y, n_nodes,
                                       ntiles);
    }

    // 3) scatter-add y[src] -> out[dst]: 8 edges/warp-iter, x2 MLP
    {
        int threads = 256;   // 8 warps
        int blocks  = 4736;
        scatter_kernel<<<blocks, threads>>>((const float4*)y, edge_index, out,
                                            n_edges);
    }
}